// round 2
// baseline (speedup 1.0000x reference)
#include <cuda_runtime.h>

// Causal FlashAttention fp32, SIMT with packed f32x2 FMA (sm_103a).
// B*H grid.y, 64-row Q tiles grid.x. Online softmax in registers.

#define BR 64
#define BC 64
#define HD 128
#define PS_STRIDE 68   // 64 + 4 pad, keeps 16B alignment (68*4 = 272 = 17*16)
#define NTHREADS 256
#define SCALE 0.08838834764831845f  // 1/sqrt(128)

typedef unsigned long long ull;

struct SmemLayout {
    float Qs[HD][BR];        // Q transposed (d-major), pre-scaled   32 KB
    float Ks[HD][BC];        // K transposed (d-major)               32 KB
    float Vs[BC][HD];        // V row-major                          32 KB
    float Ps[BR][PS_STRIDE]; // probabilities                        17 KB
};

__device__ __forceinline__ ull dup2(float x) {
    ull r; unsigned u = __float_as_uint(x);
    asm("mov.b64 %0, {%1, %1};" : "=l"(r) : "r"(u));
    return r;
}
__device__ __forceinline__ void unpack2(ull p, float& lo, float& hi) {
    unsigned a, b;
    asm("mov.b64 {%0, %1}, %2;" : "=r"(a), "=r"(b) : "l"(p));
    lo = __uint_as_float(a); hi = __uint_as_float(b);
}
__device__ __forceinline__ ull ffma2(ull a, ull b, ull c) {
    ull d;
    asm("fma.rn.f32x2 %0, %1, %2, %3;" : "=l"(d) : "l"(a), "l"(b), "l"(c));
    return d;
}
__device__ __forceinline__ ull fmul2(ull a, ull b) {
    ull d;
    asm("mul.rn.f32x2 %0, %1, %2;" : "=l"(d) : "l"(a), "l"(b));
    return d;
}

__global__ __launch_bounds__(NTHREADS, 1)
void flash_fwd_kernel(const float* __restrict__ gq,
                      const float* __restrict__ gk,
                      const float* __restrict__ gv,
                      float* __restrict__ gout,
                      int seqlen)
{
    extern __shared__ char raw[];
    SmemLayout* sm = reinterpret_cast<SmemLayout*>(raw);

    const int tid = threadIdx.x;
    const int tx = tid & 15;        // 16 col groups
    const int ty = tid >> 4;        // 16 row groups (2 per warp)
    const int bh = blockIdx.y;
    const int qtile = blockIdx.x;
    const int qbase = qtile * BR;
    const size_t bh_off = (size_t)bh * seqlen * HD;

    // ---- Load Q tile transposed into smem, folded scale ----
    {
        int r = tid & 63;           // lanes -> consecutive rows: conflict-free STS
        int cg = tid >> 6;          // 4 chunk groups
        const float* qp = gq + bh_off + (size_t)(qbase + r) * HD;
        #pragma unroll
        for (int jj = 0; jj < 8; ++jj) {
            int c = cg + jj * 4;    // float4 chunk 0..31
            float4 t = *(const float4*)(qp + c * 4);
            sm->Qs[c * 4 + 0][r] = t.x * SCALE;
            sm->Qs[c * 4 + 1][r] = t.y * SCALE;
            sm->Qs[c * 4 + 2][r] = t.z * SCALE;
            sm->Qs[c * 4 + 3][r] = t.w * SCALE;
        }
    }

    // Per-thread state: rows 4*ty..4*ty+3 (replicated across the 16 tx lanes)
    float m_r[4], l_r[4];
    ull acco[4][4];   // O accum: row r, col-pairs {4tx,4tx+1},{4tx+2,4tx+3},{64+4tx,..},{64+4tx+2,..}
    #pragma unroll
    for (int r = 0; r < 4; ++r) {
        m_r[r] = -1e30f; l_r[r] = 0.0f;
        #pragma unroll
        for (int c = 0; c < 4; ++c) acco[r][c] = 0ull;
    }

    for (int j = 0; j <= qtile; ++j) {
        const int kbase = j * BC;
        __syncthreads();   // previous-iteration readers of Ks/Vs/Ps are done

        // ---- K tile transposed ----
        {
            int r = tid & 63;
            int cg = tid >> 6;
            const float* kp = gk + bh_off + (size_t)(kbase + r) * HD;
            #pragma unroll
            for (int jj = 0; jj < 8; ++jj) {
                int c = cg + jj * 4;
                float4 t = *(const float4*)(kp + c * 4);
                sm->Ks[c * 4 + 0][r] = t.x;
                sm->Ks[c * 4 + 1][r] = t.y;
                sm->Ks[c * 4 + 2][r] = t.z;
                sm->Ks[c * 4 + 3][r] = t.w;
            }
        }
        // ---- V tile (row-major, fully coalesced both sides) ----
        {
            const float* vp = gv + bh_off + (size_t)kbase * HD;
            #pragma unroll
            for (int jj = 0; jj < 8; ++jj) {
                int idx = tid + jj * NTHREADS;   // float4 unit index
                int rr = idx >> 5, cc = idx & 31;
                *(float4*)&sm->Vs[rr][cc * 4] = *(const float4*)(vp + rr * HD + cc * 4);
            }
        }
        __syncthreads();

        // ---- S = Q @ K^T  (rows paired in f32x2) ----
        ull accs[2][4];
        #pragma unroll
        for (int p = 0; p < 2; ++p)
            #pragma unroll
            for (int c = 0; c < 4; ++c) accs[p][c] = 0ull;

        const float* qcol = &sm->Qs[0][ty * 4];
        const float* kcol = &sm->Ks[0][tx * 4];
        #pragma unroll 4
        for (int kk = 0; kk < HD; ++kk) {
            ulonglong2 av = *(const ulonglong2*)(qcol + kk * BR); // rows (4ty,4ty+1),(4ty+2,4ty+3)
            float4 bv = *(const float4*)(kcol + kk * BC);          // cols 4tx..4tx+3
            ull b0 = dup2(bv.x), b1 = dup2(bv.y), b2 = dup2(bv.z), b3 = dup2(bv.w);
            accs[0][0] = ffma2(av.x, b0, accs[0][0]);
            accs[1][0] = ffma2(av.y, b0, accs[1][0]);
            accs[0][1] = ffma2(av.x, b1, accs[0][1]);
            accs[1][1] = ffma2(av.y, b1, accs[1][1]);
            accs[0][2] = ffma2(av.x, b2, accs[0][2]);
            accs[1][2] = ffma2(av.y, b2, accs[1][2]);
            accs[0][3] = ffma2(av.x, b3, accs[0][3]);
            accs[1][3] = ffma2(av.y, b3, accs[1][3]);
        }

        float s[4][4];
        #pragma unroll
        for (int c = 0; c < 4; ++c) {
            unpack2(accs[0][c], s[0][c], s[1][c]);
            unpack2(accs[1][c], s[2][c], s[3][c]);
        }

        // ---- causal mask on the diagonal tile (local compare: bases equal) ----
        if (j == qtile) {
            #pragma unroll
            for (int rr = 0; rr < 4; ++rr)
                #pragma unroll
                for (int c = 0; c < 4; ++c)
                    if (tx * 4 + c > ty * 4 + rr) s[rr][c] = -1e30f;
        }

        // ---- online softmax (per row, reduce across the 16 tx lanes) ----
        #pragma unroll
        for (int rr = 0; rr < 4; ++rr) {
            float mx = fmaxf(fmaxf(s[rr][0], s[rr][1]), fmaxf(s[rr][2], s[rr][3]));
            #pragma unroll
            for (int off = 8; off >= 1; off >>= 1)
                mx = fmaxf(mx, __shfl_xor_sync(0xffffffffu, mx, off));
            float mn = fmaxf(m_r[rr], mx);
            float fac = __expf(m_r[rr] - mn);
            m_r[rr] = mn;

            float p0 = __expf(s[rr][0] - mn);
            float p1 = __expf(s[rr][1] - mn);
            float p2 = __expf(s[rr][2] - mn);
            float p3 = __expf(s[rr][3] - mn);
            float rs = (p0 + p1) + (p2 + p3);
            #pragma unroll
            for (int off = 8; off >= 1; off >>= 1)
                rs += __shfl_xor_sync(0xffffffffu, rs, off);
            l_r[rr] = l_r[rr] * fac + rs;

            *(float4*)&sm->Ps[ty * 4 + rr][tx * 4] = make_float4(p0, p1, p2, p3);

            ull f2 = dup2(fac);
            #pragma unroll
            for (int cp = 0; cp < 4; ++cp) acco[rr][cp] = fmul2(acco[rr][cp], f2);
        }
        __syncwarp();   // P row r is produced & consumed by the same half-warp

        // ---- O += P @ V  (cols paired in f32x2) ----
        const float* prow = &sm->Ps[ty * 4][0];
        #pragma unroll 4
        for (int kv = 0; kv < BC; ++kv) {
            float a0 = prow[kv];
            float a1 = prow[PS_STRIDE + kv];
            float a2 = prow[2 * PS_STRIDE + kv];
            float a3 = prow[3 * PS_STRIDE + kv];
            ulonglong2 blo = *(const ulonglong2*)&sm->Vs[kv][tx * 4];
            ulonglong2 bhi = *(const ulonglong2*)&sm->Vs[kv][64 + tx * 4];
            ull a0d = dup2(a0), a1d = dup2(a1), a2d = dup2(a2), a3d = dup2(a3);
            acco[0][0] = ffma2(a0d, blo.x, acco[0][0]);
            acco[0][1] = ffma2(a0d, blo.y, acco[0][1]);
            acco[0][2] = ffma2(a0d, bhi.x, acco[0][2]);
            acco[0][3] = ffma2(a0d, bhi.y, acco[0][3]);
            acco[1][0] = ffma2(a1d, blo.x, acco[1][0]);
            acco[1][1] = ffma2(a1d, blo.y, acco[1][1]);
            acco[1][2] = ffma2(a1d, bhi.x, acco[1][2]);
            acco[1][3] = ffma2(a1d, bhi.y, acco[1][3]);
            acco[2][0] = ffma2(a2d, blo.x, acco[2][0]);
            acco[2][1] = ffma2(a2d, blo.y, acco[2][1]);
            acco[2][2] = ffma2(a2d, bhi.x, acco[2][2]);
            acco[2][3] = ffma2(a2d, bhi.y, acco[2][3]);
            acco[3][0] = ffma2(a3d, blo.x, acco[3][0]);
            acco[3][1] = ffma2(a3d, blo.y, acco[3][1]);
            acco[3][2] = ffma2(a3d, bhi.x, acco[3][2]);
            acco[3][3] = ffma2(a3d, bhi.y, acco[3][3]);
        }
    }

    // ---- epilogue: O /= l, write out ----
    #pragma unroll
    for (int rr = 0; rr < 4; ++rr) {
        float inv = 1.0f / l_r[rr];
        float o[8];
        unpack2(acco[rr][0], o[0], o[1]);
        unpack2(acco[rr][1], o[2], o[3]);
        unpack2(acco[rr][2], o[4], o[5]);
        unpack2(acco[rr][3], o[6], o[7]);
        float* orow = gout + bh_off + (size_t)(qbase + ty * 4 + rr) * HD;
        *(float4*)(orow + tx * 4)      = make_float4(o[0]*inv, o[1]*inv, o[2]*inv, o[3]*inv);
        *(float4*)(orow + 64 + tx * 4) = make_float4(o[4]*inv, o[5]*inv, o[6]*inv, o[7]*inv);
    }
}

extern "C" void kernel_launch(void* const* d_in, const int* in_sizes, int n_in,
                              void* d_out, int out_size)
{
    const float* q = (const float*)d_in[0];
    const float* k = (const float*)d_in[1];
    const float* v = (const float*)d_in[2];
    float* out = (float*)d_out;

    const int seqlen = 2048;
    const int nbh = in_sizes[0] / (seqlen * HD);   // B*H = 32

    size_t smem = sizeof(SmemLayout);
    cudaFuncSetAttribute(flash_fwd_kernel,
                         cudaFuncAttributeMaxDynamicSharedMemorySize, (int)smem);

    dim3 grid(seqlen / BR, nbh);
    flash_fwd_kernel<<<grid, NTHREADS, smem>>>(q, k, v, out, seqlen);
}

// round 3
// speedup vs baseline: 1.0009x; 1.0009x over previous
#include <cuda_runtime.h>

// Causal FlashAttention fp32, SIMT with packed f32x2 FMA (sm_103a).
// B*H grid.y, 64-row Q tiles grid.x. Online softmax in registers.

#define BR 64
#define BC 64
#define HD 128
#define PS_STRIDE 68   // 64 + 4 pad, keeps 16B alignment (68*4 = 272 = 17*16)
#define NTHREADS 256
#define SCALE 0.08838834764831845f  // 1/sqrt(128)

typedef unsigned long long ull;

struct SmemLayout {
    float Qs[HD][BR];        // Q transposed (d-major), pre-scaled   32 KB
    float Ks[HD][BC];        // K transposed (d-major)               32 KB
    float Vs[BC][HD];        // V row-major                          32 KB
    float Ps[BR][PS_STRIDE]; // probabilities                        17 KB
};

__device__ __forceinline__ ull dup2(float x) {
    ull r; unsigned u = __float_as_uint(x);
    asm("mov.b64 %0, {%1, %1};" : "=l"(r) : "r"(u));
    return r;
}
__device__ __forceinline__ void unpack2(ull p, float& lo, float& hi) {
    unsigned a, b;
    asm("mov.b64 {%0, %1}, %2;" : "=r"(a), "=r"(b) : "l"(p));
    lo = __uint_as_float(a); hi = __uint_as_float(b);
}
__device__ __forceinline__ ull ffma2(ull a, ull b, ull c) {
    ull d;
    asm("fma.rn.f32x2 %0, %1, %2, %3;" : "=l"(d) : "l"(a), "l"(b), "l"(c));
    return d;
}
__device__ __forceinline__ ull fmul2(ull a, ull b) {
    ull d;
    asm("mul.rn.f32x2 %0, %1, %2;" : "=l"(d) : "l"(a), "l"(b));
    return d;
}

__global__ __launch_bounds__(NTHREADS, 1)
void flash_fwd_kernel(const float* __restrict__ gq,
                      const float* __restrict__ gk,
                      const float* __restrict__ gv,
                      float* __restrict__ gout,
                      int seqlen)
{
    extern __shared__ char raw[];
    SmemLayout* sm = reinterpret_cast<SmemLayout*>(raw);

    const int tid = threadIdx.x;
    const int tx = tid & 15;        // 16 col groups
    const int ty = tid >> 4;        // 16 row groups (2 per warp)
    const int bh = blockIdx.y;
    const int qtile = blockIdx.x;
    const int qbase = qtile * BR;
    const size_t bh_off = (size_t)bh * seqlen * HD;

    // ---- Load Q tile transposed into smem, folded scale ----
    {
        int r = tid & 63;           // lanes -> consecutive rows: conflict-free STS
        int cg = tid >> 6;          // 4 chunk groups
        const float* qp = gq + bh_off + (size_t)(qbase + r) * HD;
        #pragma unroll
        for (int jj = 0; jj < 8; ++jj) {
            int c = cg + jj * 4;    // float4 chunk 0..31
            float4 t = *(const float4*)(qp + c * 4);
            sm->Qs[c * 4 + 0][r] = t.x * SCALE;
            sm->Qs[c * 4 + 1][r] = t.y * SCALE;
            sm->Qs[c * 4 + 2][r] = t.z * SCALE;
            sm->Qs[c * 4 + 3][r] = t.w * SCALE;
        }
    }

    // Per-thread state: rows 4*ty..4*ty+3 (replicated across the 16 tx lanes)
    float m_r[4], l_r[4];
    ull acco[4][4];   // O accum: row r, col-pairs {4tx,4tx+1},{4tx+2,4tx+3},{64+4tx,..},{64+4tx+2,..}
    #pragma unroll
    for (int r = 0; r < 4; ++r) {
        m_r[r] = -1e30f; l_r[r] = 0.0f;
        #pragma unroll
        for (int c = 0; c < 4; ++c) acco[r][c] = 0ull;
    }

    for (int j = 0; j <= qtile; ++j) {
        const int kbase = j * BC;
        __syncthreads();   // previous-iteration readers of Ks/Vs/Ps are done

        // ---- K tile transposed ----
        {
            int r = tid & 63;
            int cg = tid >> 6;
            const float* kp = gk + bh_off + (size_t)(kbase + r) * HD;
            #pragma unroll
            for (int jj = 0; jj < 8; ++jj) {
                int c = cg + jj * 4;
                float4 t = *(const float4*)(kp + c * 4);
                sm->Ks[c * 4 + 0][r] = t.x;
                sm->Ks[c * 4 + 1][r] = t.y;
                sm->Ks[c * 4 + 2][r] = t.z;
                sm->Ks[c * 4 + 3][r] = t.w;
            }
        }
        // ---- V tile (row-major, fully coalesced both sides) ----
        {
            const float* vp = gv + bh_off + (size_t)kbase * HD;
            #pragma unroll
            for (int jj = 0; jj < 8; ++jj) {
                int idx = tid + jj * NTHREADS;   // float4 unit index
                int rr = idx >> 5, cc = idx & 31;
                *(float4*)&sm->Vs[rr][cc * 4] = *(const float4*)(vp + rr * HD + cc * 4);
            }
        }
        __syncthreads();

        // ---- S = Q @ K^T  (rows paired in f32x2) ----
        ull accs[2][4];
        #pragma unroll
        for (int p = 0; p < 2; ++p)
            #pragma unroll
            for (int c = 0; c < 4; ++c) accs[p][c] = 0ull;

        const float* qcol = &sm->Qs[0][ty * 4];
        const float* kcol = &sm->Ks[0][tx * 4];
        #pragma unroll 4
        for (int kk = 0; kk < HD; ++kk) {
            ulonglong2 av = *(const ulonglong2*)(qcol + kk * BR); // rows (4ty,4ty+1),(4ty+2,4ty+3)
            float4 bv = *(const float4*)(kcol + kk * BC);          // cols 4tx..4tx+3
            ull b0 = dup2(bv.x), b1 = dup2(bv.y), b2 = dup2(bv.z), b3 = dup2(bv.w);
            accs[0][0] = ffma2(av.x, b0, accs[0][0]);
            accs[1][0] = ffma2(av.y, b0, accs[1][0]);
            accs[0][1] = ffma2(av.x, b1, accs[0][1]);
            accs[1][1] = ffma2(av.y, b1, accs[1][1]);
            accs[0][2] = ffma2(av.x, b2, accs[0][2]);
            accs[1][2] = ffma2(av.y, b2, accs[1][2]);
            accs[0][3] = ffma2(av.x, b3, accs[0][3]);
            accs[1][3] = ffma2(av.y, b3, accs[1][3]);
        }

        float s[4][4];
        #pragma unroll
        for (int c = 0; c < 4; ++c) {
            unpack2(accs[0][c], s[0][c], s[1][c]);
            unpack2(accs[1][c], s[2][c], s[3][c]);
        }

        // ---- causal mask on the diagonal tile (local compare: bases equal) ----
        if (j == qtile) {
            #pragma unroll
            for (int rr = 0; rr < 4; ++rr)
                #pragma unroll
                for (int c = 0; c < 4; ++c)
                    if (tx * 4 + c > ty * 4 + rr) s[rr][c] = -1e30f;
        }

        // ---- online softmax (per row, reduce across the 16 tx lanes) ----
        #pragma unroll
        for (int rr = 0; rr < 4; ++rr) {
            float mx = fmaxf(fmaxf(s[rr][0], s[rr][1]), fmaxf(s[rr][2], s[rr][3]));
            #pragma unroll
            for (int off = 8; off >= 1; off >>= 1)
                mx = fmaxf(mx, __shfl_xor_sync(0xffffffffu, mx, off));
            float mn = fmaxf(m_r[rr], mx);
            float fac = __expf(m_r[rr] - mn);
            m_r[rr] = mn;

            float p0 = __expf(s[rr][0] - mn);
            float p1 = __expf(s[rr][1] - mn);
            float p2 = __expf(s[rr][2] - mn);
            float p3 = __expf(s[rr][3] - mn);
            float rs = (p0 + p1) + (p2 + p3);
            #pragma unroll
            for (int off = 8; off >= 1; off >>= 1)
                rs += __shfl_xor_sync(0xffffffffu, rs, off);
            l_r[rr] = l_r[rr] * fac + rs;

            *(float4*)&sm->Ps[ty * 4 + rr][tx * 4] = make_float4(p0, p1, p2, p3);

            ull f2 = dup2(fac);
            #pragma unroll
            for (int cp = 0; cp < 4; ++cp) acco[rr][cp] = fmul2(acco[rr][cp], f2);
        }
        __syncwarp();   // P row r is produced & consumed by the same half-warp

        // ---- O += P @ V  (cols paired in f32x2) ----
        const float* prow = &sm->Ps[ty * 4][0];
        #pragma unroll 4
        for (int kv = 0; kv < BC; ++kv) {
            float a0 = prow[kv];
            float a1 = prow[PS_STRIDE + kv];
            float a2 = prow[2 * PS_STRIDE + kv];
            float a3 = prow[3 * PS_STRIDE + kv];
            ulonglong2 blo = *(const ulonglong2*)&sm->Vs[kv][tx * 4];
            ulonglong2 bhi = *(const ulonglong2*)&sm->Vs[kv][64 + tx * 4];
            ull a0d = dup2(a0), a1d = dup2(a1), a2d = dup2(a2), a3d = dup2(a3);
            acco[0][0] = ffma2(a0d, blo.x, acco[0][0]);
            acco[0][1] = ffma2(a0d, blo.y, acco[0][1]);
            acco[0][2] = ffma2(a0d, bhi.x, acco[0][2]);
            acco[0][3] = ffma2(a0d, bhi.y, acco[0][3]);
            acco[1][0] = ffma2(a1d, blo.x, acco[1][0]);
            acco[1][1] = ffma2(a1d, blo.y, acco[1][1]);
            acco[1][2] = ffma2(a1d, bhi.x, acco[1][2]);
            acco[1][3] = ffma2(a1d, bhi.y, acco[1][3]);
            acco[2][0] = ffma2(a2d, blo.x, acco[2][0]);
            acco[2][1] = ffma2(a2d, blo.y, acco[2][1]);
            acco[2][2] = ffma2(a2d, bhi.x, acco[2][2]);
            acco[2][3] = ffma2(a2d, bhi.y, acco[2][3]);
            acco[3][0] = ffma2(a3d, blo.x, acco[3][0]);
            acco[3][1] = ffma2(a3d, blo.y, acco[3][1]);
            acco[3][2] = ffma2(a3d, bhi.x, acco[3][2]);
            acco[3][3] = ffma2(a3d, bhi.y, acco[3][3]);
        }
    }

    // ---- epilogue: O /= l, write out ----
    #pragma unroll
    for (int rr = 0; rr < 4; ++rr) {
        float inv = 1.0f / l_r[rr];
        float o[8];
        unpack2(acco[rr][0], o[0], o[1]);
        unpack2(acco[rr][1], o[2], o[3]);
        unpack2(acco[rr][2], o[4], o[5]);
        unpack2(acco[rr][3], o[6], o[7]);
        float* orow = gout + bh_off + (size_t)(qbase + ty * 4 + rr) * HD;
        *(float4*)(orow + tx * 4)      = make_float4(o[0]*inv, o[1]*inv, o[2]*inv, o[3]*inv);
        *(float4*)(orow + 64 + tx * 4) = make_float4(o[4]*inv, o[5]*inv, o[6]*inv, o[7]*inv);
    }
}

extern "C" void kernel_launch(void* const* d_in, const int* in_sizes, int n_in,
                              void* d_out, int out_size)
{
    const float* q = (const float*)d_in[0];
    const float* k = (const float*)d_in[1];
    const float* v = (const float*)d_in[2];
    float* out = (float*)d_out;

    const int seqlen = 2048;
    const int nbh = in_sizes[0] / (seqlen * HD);   // B*H = 32

    size_t smem = sizeof(SmemLayout);
    cudaFuncSetAttribute(flash_fwd_kernel,
                         cudaFuncAttributeMaxDynamicSharedMemorySize, (int)smem);

    dim3 grid(seqlen / BR, nbh);
    flash_fwd_kernel<<<grid, NTHREADS, smem>>>(q, k, v, out, seqlen);
}

// round 4
// speedup vs baseline: 1.0020x; 1.0011x over previous
#include <cuda_runtime.h>

// Causal FlashAttention fp32, SIMT with packed f32x2 FMA (sm_103a).
// B*H grid.y, 64-row Q tiles grid.x. Online softmax in registers.

#define BR 64
#define BC 64
#define HD 128
#define PS_STRIDE 68   // 64 + 4 pad, keeps 16B alignment (68*4 = 272 = 17*16)
#define NTHREADS 256
#define SCALE 0.08838834764831845f  // 1/sqrt(128)

typedef unsigned long long ull;

struct SmemLayout {
    float Qs[HD][BR];        // Q transposed (d-major), pre-scaled   32 KB
    float Ks[HD][BC];        // K transposed (d-major)               32 KB
    float Vs[BC][HD];        // V row-major                          32 KB
    float Ps[BR][PS_STRIDE]; // probabilities                        17 KB
};

__device__ __forceinline__ ull dup2(float x) {
    ull r; unsigned u = __float_as_uint(x);
    asm("mov.b64 %0, {%1, %1};" : "=l"(r) : "r"(u));
    return r;
}
__device__ __forceinline__ void unpack2(ull p, float& lo, float& hi) {
    unsigned a, b;
    asm("mov.b64 {%0, %1}, %2;" : "=r"(a), "=r"(b) : "l"(p));
    lo = __uint_as_float(a); hi = __uint_as_float(b);
}
__device__ __forceinline__ ull ffma2(ull a, ull b, ull c) {
    ull d;
    asm("fma.rn.f32x2 %0, %1, %2, %3;" : "=l"(d) : "l"(a), "l"(b), "l"(c));
    return d;
}
__device__ __forceinline__ ull fmul2(ull a, ull b) {
    ull d;
    asm("mul.rn.f32x2 %0, %1, %2;" : "=l"(d) : "l"(a), "l"(b));
    return d;
}

__global__ __launch_bounds__(NTHREADS, 1)
void flash_fwd_kernel(const float* __restrict__ gq,
                      const float* __restrict__ gk,
                      const float* __restrict__ gv,
                      float* __restrict__ gout,
                      int seqlen)
{
    extern __shared__ char raw[];
    SmemLayout* sm = reinterpret_cast<SmemLayout*>(raw);

    const int tid = threadIdx.x;
    const int tx = tid & 15;        // 16 col groups
    const int ty = tid >> 4;        // 16 row groups (2 per warp)
    const int bh = blockIdx.y;
    const int qtile = blockIdx.x;
    const int qbase = qtile * BR;
    const size_t bh_off = (size_t)bh * seqlen * HD;

    // ---- Load Q tile transposed into smem, folded scale ----
    {
        int r = tid & 63;           // lanes -> consecutive rows: conflict-free STS
        int cg = tid >> 6;          // 4 chunk groups
        const float* qp = gq + bh_off + (size_t)(qbase + r) * HD;
        #pragma unroll
        for (int jj = 0; jj < 8; ++jj) {
            int c = cg + jj * 4;    // float4 chunk 0..31
            float4 t = *(const float4*)(qp + c * 4);
            sm->Qs[c * 4 + 0][r] = t.x * SCALE;
            sm->Qs[c * 4 + 1][r] = t.y * SCALE;
            sm->Qs[c * 4 + 2][r] = t.z * SCALE;
            sm->Qs[c * 4 + 3][r] = t.w * SCALE;
        }
    }

    // Per-thread state: rows 4*ty..4*ty+3 (replicated across the 16 tx lanes)
    float m_r[4], l_r[4];
    ull acco[4][4];   // O accum: row r, col-pairs {4tx,4tx+1},{4tx+2,4tx+3},{64+4tx,..},{64+4tx+2,..}
    #pragma unroll
    for (int r = 0; r < 4; ++r) {
        m_r[r] = -1e30f; l_r[r] = 0.0f;
        #pragma unroll
        for (int c = 0; c < 4; ++c) acco[r][c] = 0ull;
    }

    for (int j = 0; j <= qtile; ++j) {
        const int kbase = j * BC;
        __syncthreads();   // previous-iteration readers of Ks/Vs/Ps are done

        // ---- K tile transposed ----
        {
            int r = tid & 63;
            int cg = tid >> 6;
            const float* kp = gk + bh_off + (size_t)(kbase + r) * HD;
            #pragma unroll
            for (int jj = 0; jj < 8; ++jj) {
                int c = cg + jj * 4;
                float4 t = *(const float4*)(kp + c * 4);
                sm->Ks[c * 4 + 0][r] = t.x;
                sm->Ks[c * 4 + 1][r] = t.y;
                sm->Ks[c * 4 + 2][r] = t.z;
                sm->Ks[c * 4 + 3][r] = t.w;
            }
        }
        // ---- V tile (row-major, fully coalesced both sides) ----
        {
            const float* vp = gv + bh_off + (size_t)kbase * HD;
            #pragma unroll
            for (int jj = 0; jj < 8; ++jj) {
                int idx = tid + jj * NTHREADS;   // float4 unit index
                int rr = idx >> 5, cc = idx & 31;
                *(float4*)&sm->Vs[rr][cc * 4] = *(const float4*)(vp + rr * HD + cc * 4);
            }
        }
        __syncthreads();

        // ---- S = Q @ K^T  (rows paired in f32x2) ----
        ull accs[2][4];
        #pragma unroll
        for (int p = 0; p < 2; ++p)
            #pragma unroll
            for (int c = 0; c < 4; ++c) accs[p][c] = 0ull;

        const float* qcol = &sm->Qs[0][ty * 4];
        const float* kcol = &sm->Ks[0][tx * 4];
        #pragma unroll 4
        for (int kk = 0; kk < HD; ++kk) {
            ulonglong2 av = *(const ulonglong2*)(qcol + kk * BR); // rows (4ty,4ty+1),(4ty+2,4ty+3)
            float4 bv = *(const float4*)(kcol + kk * BC);          // cols 4tx..4tx+3
            ull b0 = dup2(bv.x), b1 = dup2(bv.y), b2 = dup2(bv.z), b3 = dup2(bv.w);
            accs[0][0] = ffma2(av.x, b0, accs[0][0]);
            accs[1][0] = ffma2(av.y, b0, accs[1][0]);
            accs[0][1] = ffma2(av.x, b1, accs[0][1]);
            accs[1][1] = ffma2(av.y, b1, accs[1][1]);
            accs[0][2] = ffma2(av.x, b2, accs[0][2]);
            accs[1][2] = ffma2(av.y, b2, accs[1][2]);
            accs[0][3] = ffma2(av.x, b3, accs[0][3]);
            accs[1][3] = ffma2(av.y, b3, accs[1][3]);
        }

        float s[4][4];
        #pragma unroll
        for (int c = 0; c < 4; ++c) {
            unpack2(accs[0][c], s[0][c], s[1][c]);
            unpack2(accs[1][c], s[2][c], s[3][c]);
        }

        // ---- causal mask on the diagonal tile (local compare: bases equal) ----
        if (j == qtile) {
            #pragma unroll
            for (int rr = 0; rr < 4; ++rr)
                #pragma unroll
                for (int c = 0; c < 4; ++c)
                    if (tx * 4 + c > ty * 4 + rr) s[rr][c] = -1e30f;
        }

        // ---- online softmax (per row, reduce across the 16 tx lanes) ----
        #pragma unroll
        for (int rr = 0; rr < 4; ++rr) {
            float mx = fmaxf(fmaxf(s[rr][0], s[rr][1]), fmaxf(s[rr][2], s[rr][3]));
            #pragma unroll
            for (int off = 8; off >= 1; off >>= 1)
                mx = fmaxf(mx, __shfl_xor_sync(0xffffffffu, mx, off));
            float mn = fmaxf(m_r[rr], mx);
            float fac = __expf(m_r[rr] - mn);
            m_r[rr] = mn;

            float p0 = __expf(s[rr][0] - mn);
            float p1 = __expf(s[rr][1] - mn);
            float p2 = __expf(s[rr][2] - mn);
            float p3 = __expf(s[rr][3] - mn);
            float rs = (p0 + p1) + (p2 + p3);
            #pragma unroll
            for (int off = 8; off >= 1; off >>= 1)
                rs += __shfl_xor_sync(0xffffffffu, rs, off);
            l_r[rr] = l_r[rr] * fac + rs;

            *(float4*)&sm->Ps[ty * 4 + rr][tx * 4] = make_float4(p0, p1, p2, p3);

            ull f2 = dup2(fac);
            #pragma unroll
            for (int cp = 0; cp < 4; ++cp) acco[rr][cp] = fmul2(acco[rr][cp], f2);
        }
        __syncwarp();   // P row r is produced & consumed by the same half-warp

        // ---- O += P @ V  (cols paired in f32x2) ----
        const float* prow = &sm->Ps[ty * 4][0];
        #pragma unroll 4
        for (int kv = 0; kv < BC; ++kv) {
            float a0 = prow[kv];
            float a1 = prow[PS_STRIDE + kv];
            float a2 = prow[2 * PS_STRIDE + kv];
            float a3 = prow[3 * PS_STRIDE + kv];
            ulonglong2 blo = *(const ulonglong2*)&sm->Vs[kv][tx * 4];
            ulonglong2 bhi = *(const ulonglong2*)&sm->Vs[kv][64 + tx * 4];
            ull a0d = dup2(a0), a1d = dup2(a1), a2d = dup2(a2), a3d = dup2(a3);
            acco[0][0] = ffma2(a0d, blo.x, acco[0][0]);
            acco[0][1] = ffma2(a0d, blo.y, acco[0][1]);
            acco[0][2] = ffma2(a0d, bhi.x, acco[0][2]);
            acco[0][3] = ffma2(a0d, bhi.y, acco[0][3]);
            acco[1][0] = ffma2(a1d, blo.x, acco[1][0]);
            acco[1][1] = ffma2(a1d, blo.y, acco[1][1]);
            acco[1][2] = ffma2(a1d, bhi.x, acco[1][2]);
            acco[1][3] = ffma2(a1d, bhi.y, acco[1][3]);
            acco[2][0] = ffma2(a2d, blo.x, acco[2][0]);
            acco[2][1] = ffma2(a2d, blo.y, acco[2][1]);
            acco[2][2] = ffma2(a2d, bhi.x, acco[2][2]);
            acco[2][3] = ffma2(a2d, bhi.y, acco[2][3]);
            acco[3][0] = ffma2(a3d, blo.x, acco[3][0]);
            acco[3][1] = ffma2(a3d, blo.y, acco[3][1]);
            acco[3][2] = ffma2(a3d, bhi.x, acco[3][2]);
            acco[3][3] = ffma2(a3d, bhi.y, acco[3][3]);
        }
    }

    // ---- epilogue: O /= l, write out ----
    #pragma unroll
    for (int rr = 0; rr < 4; ++rr) {
        float inv = 1.0f / l_r[rr];
        float o[8];
        unpack2(acco[rr][0], o[0], o[1]);
        unpack2(acco[rr][1], o[2], o[3]);
        unpack2(acco[rr][2], o[4], o[5]);
        unpack2(acco[rr][3], o[6], o[7]);
        float* orow = gout + bh_off + (size_t)(qbase + ty * 4 + rr) * HD;
        *(float4*)(orow + tx * 4)      = make_float4(o[0]*inv, o[1]*inv, o[2]*inv, o[3]*inv);
        *(float4*)(orow + 64 + tx * 4) = make_float4(o[4]*inv, o[5]*inv, o[6]*inv, o[7]*inv);
    }
}

extern "C" void kernel_launch(void* const* d_in, const int* in_sizes, int n_in,
                              void* d_out, int out_size)
{
    const float* q = (const float*)d_in[0];
    const float* k = (const float*)d_in[1];
    const float* v = (const float*)d_in[2];
    float* out = (float*)d_out;

    const int seqlen = 2048;
    const int nbh = in_sizes[0] / (seqlen * HD);   // B*H = 32

    size_t smem = sizeof(SmemLayout);
    cudaFuncSetAttribute(flash_fwd_kernel,
                         cudaFuncAttributeMaxDynamicSharedMemorySize, (int)smem);

    dim3 grid(seqlen / BR, nbh);
    flash_fwd_kernel<<<grid, NTHREADS, smem>>>(q, k, v, out, seqlen);
}